// round 6
// baseline (speedup 1.0000x reference)
#include <cuda_runtime.h>
#include <math.h>

#define NB 16
#define NC 256
#define NE 9216
#define NE4 (NE / 4)
#define KSEL 4096
#define CTAS_PER_MESH (NE4 / 32)   // 72

// Scratch (no allocations allowed) — device globals.
__device__ float4 g_score4[NB * NE4];   // scores, viewed as float[NB*NE]
__device__ int4   g_pos4[NB * NE4];     // pos[e] = output slot if kept, -1 if dropped
__device__ unsigned int g_done[NB];     // zero-initialized; reset by selector each run

// Monotone float->uint order transform (valid scores >= 0 -> >= 0x80000000).
__device__ __forceinline__ unsigned int fkey(float f) {
    unsigned int b = __float_as_uint(f);
    return (b & 0x80000000u) ? ~b : (b | 0x80000000u);
}

// ---------------------------------------------------------------------------
// Block exclusive scan over 256 threads (8 warps). wsum is shared[8].
// ---------------------------------------------------------------------------
__device__ __forceinline__ int block_exscan256(int val, int t, int* wsum) {
    int lane = t & 31, w = t >> 5;
    int x = val;
#pragma unroll
    for (int d = 1; d < 32; d <<= 1) {
        int y = __shfl_up_sync(0xFFFFFFFFu, x, d);
        if (lane >= d) x += y;
    }
    __syncthreads();               // protect wsum reuse across calls
    if (lane == 31) wsum[w] = x;   // inclusive warp total
    __syncthreads();
    if (t < 8) {
        int s = wsum[t];
        int xs = s;
#pragma unroll
        for (int d = 1; d < 8; d <<= 1) {
            int y = __shfl_up_sync(0xFFu, xs, d);
            if (t >= d) xs += y;
        }
        wsum[t] = xs - s;          // exclusive warp offsets
    }
    __syncthreads();
    return wsum[w] + x - val;      // exclusive for this thread
}

// ---------------------------------------------------------------------------
// Kernel A: score + (last CTA per mesh) select.
// grid = (72, 16), block = 256.
// Score: 32 e4-lanes x 8 channel-groups of 32 channels; SMEM reduce.
// Select: MSD radix select (4x8-bit) over gmem scores, per-warp histogram
// replicas (zero cross-warp contention), stable tie-break, position map.
// ---------------------------------------------------------------------------
__global__ __launch_bounds__(256) void score_select_kernel(
        const float4* __restrict__ x4, const void* __restrict__ ec_raw) {
    __shared__ float4 part[8][32];
    __shared__ unsigned int hist8[8][256];   // 8 KB
    __shared__ unsigned int chunksum[8];
    __shared__ unsigned int choff[8];
    __shared__ unsigned int bcast[3];
    __shared__ int wsum[8];

    const int t    = threadIdx.x;
    const int lane = t & 31;
    const int w    = t >> 5;           // warp 0..7
    const int b    = blockIdx.y;

    // ---------------- score phase ----------------
    {
        const int el = lane;           // e4 lane within block (32 lanes)
        const int cg = w;              // channel group 0..7
        const int e4 = blockIdx.x * 32 + el;
        const float4* p = x4 + ((size_t)b * NC + (size_t)cg * 32) * NE4 + e4;
        float ax = 0.f, ay = 0.f, az = 0.f, aw = 0.f;
#pragma unroll 8
        for (int c = 0; c < 32; ++c) {
            float4 v = __ldg(p + (size_t)c * NE4);
            ax = fmaf(v.x, v.x, ax);
            ay = fmaf(v.y, v.y, ay);
            az = fmaf(v.z, v.z, az);
            aw = fmaf(v.w, v.w, aw);
        }
        part[cg][el] = make_float4(ax, ay, az, aw);
        __syncthreads();
        if (t < 32) {
            float4 s = part[0][t];
#pragma unroll
            for (int g = 1; g < 8; ++g) {
                float4 q = part[g][t];
                s.x += q.x; s.y += q.y; s.z += q.z; s.w += q.w;
            }
            g_score4[b * NE4 + blockIdx.x * 32 + t] = s;
        }
        __syncthreads();
    }

    // ---------------- arrive; last CTA of this mesh becomes the selector ----
    if (t == 0) {
        __threadfence();                               // publish score writes
        bcast[2] = atomicAdd(&g_done[b], 1u);
    }
    __syncthreads();
    if (bcast[2] != CTAS_PER_MESH - 1) return;         // not last -> done
    __threadfence();                                   // acquire peers' scores

    // ---------------- select phase (one CTA, 256 threads) ----------------
    // edges_count dtype robustness: int64 vs int32 (jax x64 demotion).
    // Counts are always >= 8704, never 0, so ec32[1]==0 <=> int64 layout.
    const int* ec32 = (const int*)ec_raw;
    long long cnt;
    if (ec32[1] == 0) cnt = ((const long long*)ec_raw)[b];
    else              cnt = (long long)ec32[b];

    const float* score = (const float*)g_score4 + b * NE;

    // 4-pass MSD radix select for the KSEL-th largest key.
    unsigned int prefix = 0, pmask = 0;
    int kth = KSEL;
    for (int shift = 24; shift >= 0; shift -= 8) {
#pragma unroll
        for (int i = 0; i < 8; ++i) ((unsigned int*)hist8)[t + i * 256] = 0;
        __syncthreads();
#pragma unroll 4
        for (int e = t; e < NE; e += 256) {            // 36 uniform iterations
            unsigned int key = (e < cnt) ? fkey(__ldg(score + e)) : 0u;
            bool ok = ((key & pmask) == prefix);
            unsigned int digit = (key >> shift) & 255u;
            unsigned int active = __ballot_sync(0xFFFFFFFFu, ok);
            if (ok) {
                unsigned int peers = __match_any_sync(active, digit);
                if (lane == __ffs(peers) - 1)
                    atomicAdd(&hist8[w][digit], (unsigned int)__popc(peers));
            }
        }
        __syncthreads();
        // Merge 8 replicas; warp w owns bins [w*32, w*32+32); warp suffix scan.
        unsigned int h = 0;
        {
            const int bin = w * 32 + lane;
#pragma unroll
            for (int r = 0; r < 8; ++r) h += hist8[r][bin];
        }
        unsigned int s = h;
#pragma unroll
        for (int d = 1; d < 32; d <<= 1) {
            unsigned int y = __shfl_down_sync(0xFFFFFFFFu, s, d);
            if (lane + d < 32) s += y;
        }
        if (lane == 0) chunksum[w] = s;
        __syncthreads();
        if (t < 8) {                                   // exclusive chunk suffix
            unsigned int cs = chunksum[t], sf = cs;
#pragma unroll
            for (int d = 1; d < 8; d <<= 1) {
                unsigned int y = __shfl_down_sync(0xFFu, sf, d);
                if (t + d < 8) sf += y;
            }
            choff[t] = sf - cs;
        }
        __syncthreads();
        {
            unsigned int Sv = s + choff[w];            // suffix count from bin
            unsigned int Sn = Sv - h;                  // suffix count from bin+1
            if ((int)Sv >= kth && (int)Sn < kth) {     // exactly one bin matches
                bcast[0] = (unsigned int)(w * 32 + lane);
                bcast[1] = (unsigned int)(kth - (int)Sn);
            }
        }
        __syncthreads();
        prefix |= bcast[0] << shift;
        pmask  |= 0xFFu << shift;
        kth = (int)bcast[1];
        __syncthreads();
    }

    const unsigned int T = prefix;   // key of the KSEL-th largest element
    const int needed_eq = kth;       // # of ==T elements to keep (lowest idx first)

    // Per-thread contiguous chunk of 36 elements (256 * 36 = 9216).
    // Keys reloaded from L1-hot gmem each pass (36 regs would spill).
    const int base = t * 36;

    int eqcnt = 0;
    for (int i = 0; i < 36; ++i) {
        int e = base + i;
        unsigned int key = (e < cnt) ? fkey(__ldg(score + e)) : 0u;
        eqcnt += (key == T);
    }
    int eqoff = block_exscan256(eqcnt, t, wsum);

    int kcnt = 0;
    {
        int eq = eqoff;
        for (int i = 0; i < 36; ++i) {
            int e = base + i;
            unsigned int key = (e < cnt) ? fkey(__ldg(score + e)) : 0u;
            bool kp = (key > T) || (key == T && eq < needed_eq);
            eq += (key == T);
            kcnt += kp;
        }
    }
    int koff = block_exscan256(kcnt, t, wsum);

    {
        int* pos = (int*)g_pos4 + b * NE;
        int eq = eqoff, k = koff;
        for (int i = 0; i < 36; ++i) {
            int e = base + i;
            unsigned int key = (e < cnt) ? fkey(__ldg(score + e)) : 0u;
            bool kp = (key > T) || (key == T && eq < needed_eq);
            eq += (key == T);
            pos[e] = kp ? k : -1;
            k += kp;
        }
    }

    if (t == 0) g_done[b] = 0;       // reset for next graph replay (deterministic)
}

// ---------------------------------------------------------------------------
// Kernel B: forward scatter — fully coalesced float4 reads of x; kept
// elements written to their dense ascending output slots (L2 merges the
// predicated STG.32s into full dirty sectors).
// grid = (NE4/256, NC/8, NB), block = 256. pos reused across 8 channels.
// ---------------------------------------------------------------------------
__global__ void scatter_kernel(const float4* __restrict__ x4,
                               float* __restrict__ out) {
    int e4 = blockIdx.x * blockDim.x + threadIdx.x;  // 0..NE4-1
    int c0 = blockIdx.y * 8;
    int b  = blockIdx.z;

    int4 pos = g_pos4[b * NE4 + e4];
    const float4* xp = x4 + ((size_t)b * NC + c0) * NE4 + e4;
    float* op = out + ((size_t)b * NC + c0) * KSEL;

#pragma unroll
    for (int j = 0; j < 8; ++j) {
        float4 v = __ldg(xp + (size_t)j * NE4);
        float* o = op + (size_t)j * KSEL;
        if (pos.x >= 0) o[pos.x] = v.x;
        if (pos.y >= 0) o[pos.y] = v.y;
        if (pos.z >= 0) o[pos.z] = v.z;
        if (pos.w >= 0) o[pos.w] = v.w;
    }
}

// ---------------------------------------------------------------------------
extern "C" void kernel_launch(void* const* d_in, const int* in_sizes, int n_in,
                              void* d_out, int out_size) {
    const float4* x4 = (const float4*)d_in[0];
    const void* ec = d_in[1];     // edges_count (int64 or int32; detected on device)
    float* out = (float*)d_out;

    score_select_kernel<<<dim3(CTAS_PER_MESH, NB), 256>>>(x4, ec);
    scatter_kernel<<<dim3(NE4 / 256, NC / 8, NB), 256>>>(x4, out);
}

// round 7
// speedup vs baseline: 1.9625x; 1.9625x over previous
#include <cuda_runtime.h>
#include <math.h>

#define NB 16
#define NC 256
#define NE 9216
#define NE4 (NE / 4)
#define KSEL 4096

// Scratch (no allocations allowed) — device globals, 16B-aligned via vector types.
__device__ float4 g_score4[NB * NE4];   // scores, viewed as float[NB*NE]
__device__ int4   g_pos4[NB * NE4];     // pos[e] = output slot if kept, -1 if dropped

// ---------------------------------------------------------------------------
// Kernel 1: score[b,e] = sum_c x[b,c,e]^2   (float4 over e, channel-split x8)
// grid = (NE4/32, NB) = (72, 16) = 1152 CTAs, block = 256.
// block = 32 e4-lanes x 8 channel-groups of 32 channels; SMEM reduce at end.
// ---------------------------------------------------------------------------
__global__ __launch_bounds__(256) void score_kernel(const float4* __restrict__ x4) {
    __shared__ float4 part[8][32];
    const int tid = threadIdx.x;
    const int el  = tid & 31;          // e4 lane within block
    const int cg  = tid >> 5;          // channel group 0..7
    const int e4  = blockIdx.x * 32 + el;
    const int b   = blockIdx.y;

    const float4* p = x4 + ((size_t)b * NC + (size_t)cg * 32) * NE4 + e4;
    float ax = 0.f, ay = 0.f, az = 0.f, aw = 0.f;
#pragma unroll 8
    for (int c = 0; c < 32; ++c) {
        float4 v = __ldg(p + (size_t)c * NE4);
        ax = fmaf(v.x, v.x, ax);
        ay = fmaf(v.y, v.y, ay);
        az = fmaf(v.z, v.z, az);
        aw = fmaf(v.w, v.w, aw);
    }
    part[cg][el] = make_float4(ax, ay, az, aw);
    __syncthreads();
    if (tid < 32) {
        float4 s = part[0][tid];
#pragma unroll
        for (int g = 1; g < 8; ++g) {
            float4 q = part[g][tid];
            s.x += q.x; s.y += q.y; s.z += q.z; s.w += q.w;
        }
        g_score4[b * NE4 + blockIdx.x * 32 + tid] = s;
    }
}

// ---------------------------------------------------------------------------
// Block exclusive scan over 1024 threads (32 warps). wsum is shared[32].
// ---------------------------------------------------------------------------
__device__ __forceinline__ int block_exscan(int val, int t, int* wsum) {
    int lane = t & 31, w = t >> 5;
    int x = val;
#pragma unroll
    for (int d = 1; d < 32; d <<= 1) {
        int y = __shfl_up_sync(0xFFFFFFFFu, x, d);
        if (lane >= d) x += y;
    }
    __syncthreads();               // protect wsum reuse across calls
    if (lane == 31) wsum[w] = x;   // inclusive warp total
    __syncthreads();
    if (w == 0) {
        int s = wsum[lane];
        int xs = s;
#pragma unroll
        for (int d = 1; d < 32; d <<= 1) {
            int y = __shfl_up_sync(0xFFFFFFFFu, xs, d);
            if (lane >= d) xs += y;
        }
        wsum[lane] = xs - s;       // exclusive warp offsets
    }
    __syncthreads();
    return wsum[w] + x - val;      // exclusive for this thread
}

// ---------------------------------------------------------------------------
// Kernel 2: per-mesh K-th-largest threshold (MSD radix select, 4x8-bit) +
// stable tie-break by ascending index + forward position map.
// One CTA of 1024 threads per mesh (16 CTAs total). Low-latency:
//  - SMEM-resident keys (single gmem read)
//  - 8-replica histogram (replica = warp&7) kills same-address ATOMS chains
//  - warp-shuffle suffix scans -> 5 __syncthreads per radix pass
// ---------------------------------------------------------------------------
__global__ __launch_bounds__(1024) void select_kernel(const void* __restrict__ ec_raw) {
    __shared__ unsigned int skey[NE];        // 36 KB
    __shared__ unsigned int hist8[8][256];   // 8 KB, replicated histogram
    __shared__ unsigned int chunksum[8];
    __shared__ unsigned int choff[8];
    __shared__ unsigned int bcast[2];
    __shared__ int wsum[32];

    const int t = threadIdx.x;
    const int lane = t & 31, w = t >> 5;
    const int b = blockIdx.x;

    // edges_count dtype robustness: int64 vs int32 (jax x64 demotion).
    // Counts are always >= 8704, never 0, so ec32[1]==0 <=> int64 layout.
    const int* ec32 = (const int*)ec_raw;
    long long cnt;
    if (ec32[1] == 0) cnt = ((const long long*)ec_raw)[b];
    else              cnt = (long long)ec32[b];

    // Load order-transformed keys (monotone float->uint; invalid edges -> 0,
    // below any valid non-negative score which maps to >= 0x80000000).
    const float* score = (const float*)g_score4;
#pragma unroll
    for (int e = t; e < NE; e += 1024) {
        unsigned int bits = 0u;
        if (e < cnt) {
            bits = __float_as_uint(score[b * NE + e]);
            bits = (bits & 0x80000000u) ? ~bits : (bits | 0x80000000u);
        }
        skey[e] = bits;
    }

    // 4-pass MSD radix select for the KSEL-th largest key.
    unsigned int prefix = 0, pmask = 0;
    int kth = KSEL;
    for (int shift = 24; shift >= 0; shift -= 8) {
        {   // clear 2048 histogram words (2 per thread)
            ((unsigned int*)hist8)[t] = 0;
            ((unsigned int*)hist8)[t + 1024] = 0;
        }
        __syncthreads();    // (also covers skey store on first pass)
#pragma unroll
        for (int e = t; e < NE; e += 1024) {   // exactly 9 uniform iterations
            unsigned int key = skey[e];
            bool ok = ((key & pmask) == prefix);
            unsigned int digit = (key >> shift) & 255u;
            unsigned int active = __ballot_sync(0xFFFFFFFFu, ok);
            if (ok) {
                unsigned int peers = __match_any_sync(active, digit);
                if (lane == __ffs(peers) - 1)
                    atomicAdd(&hist8[w & 7][digit], (unsigned int)__popc(peers));
            }
        }
        __syncthreads();
        // Warps 0..7: bin v = w*32+lane. Merge replicas, warp suffix scan.
        unsigned int h = 0, s = 0;
        if (w < 8) {
            const int bin = w * 32 + lane;
#pragma unroll
            for (int r = 0; r < 8; ++r) h += hist8[r][bin];
            s = h;                                  // inclusive suffix in chunk
#pragma unroll
            for (int d = 1; d < 32; d <<= 1) {
                unsigned int y = __shfl_down_sync(0xFFFFFFFFu, s, d);
                if (lane + d < 32) s += y;
            }
            if (lane == 0) chunksum[w] = s;         // chunk total
        }
        __syncthreads();
        if (t < 8) {                                 // exclusive suffix of chunks
            unsigned int cs = chunksum[t], sf = cs;
#pragma unroll
            for (int d = 1; d < 8; d <<= 1) {
                unsigned int y = __shfl_down_sync(0xFFu, sf, d);
                if (t + d < 8) sf += y;
            }
            choff[t] = sf - cs;
        }
        __syncthreads();
        if (w < 8) {
            unsigned int Sv = s + choff[w];          // suffix count from bin v
            unsigned int Sn = Sv - h;                // suffix count from v+1
            if ((int)Sv >= kth && (int)Sn < kth) {   // exactly one bin matches
                bcast[0] = (unsigned int)(w * 32 + lane);
                bcast[1] = (unsigned int)(kth - (int)Sn);
            }
        }
        __syncthreads();
        prefix |= bcast[0] << shift;
        pmask  |= 0xFFu << shift;
        kth = (int)bcast[1];
        __syncthreads();
    }

    const unsigned int T = prefix;   // key of the KSEL-th largest element
    const int needed_eq = kth;       // # of ==T elements to keep (lowest idx first)

    // Per-thread contiguous chunk of 9 elements (1024 * 9 = 9216).
    const int base = t * 9;
    unsigned int keys[9];
#pragma unroll
    for (int i = 0; i < 9; ++i) keys[i] = skey[base + i];

    // Pass A: rank among ==T elements (index order).
    int eqpre[9]; int eqcnt = 0;
#pragma unroll
    for (int i = 0; i < 9; ++i) { eqpre[i] = eqcnt; eqcnt += (keys[i] == T); }
    int eqoff = block_exscan(eqcnt, t, wsum);

    // Pass B: keep-flag compaction -> forward position map.
    int kpre[9]; int kcnt = 0;
#pragma unroll
    for (int i = 0; i < 9; ++i) {
        bool keep = (keys[i] > T) || (keys[i] == T && (eqoff + eqpre[i]) < needed_eq);
        kpre[i] = kcnt; kcnt += keep;
    }
    int koff = block_exscan(kcnt, t, wsum);
    int* pos = (int*)g_pos4;
#pragma unroll
    for (int i = 0; i < 9; ++i) {
        bool keep = (keys[i] > T) || (keys[i] == T && (eqoff + eqpre[i]) < needed_eq);
        pos[b * NE + base + i] = keep ? (koff + kpre[i]) : -1;
    }
}

// ---------------------------------------------------------------------------
// Kernel 3: forward scatter — fully coalesced float4 reads of x; kept
// elements written to their dense ascending output slots (L2 merges the
// predicated STG.32s into full dirty sectors).
// grid = (NE4/256, NC/8, NB), block = 256. pos reused across 8 channels.
// ---------------------------------------------------------------------------
__global__ void scatter_kernel(const float4* __restrict__ x4,
                               float* __restrict__ out) {
    int e4 = blockIdx.x * blockDim.x + threadIdx.x;  // 0..NE4-1
    int c0 = blockIdx.y * 8;
    int b  = blockIdx.z;

    int4 pos = g_pos4[b * NE4 + e4];
    const float4* xp = x4 + ((size_t)b * NC + c0) * NE4 + e4;
    float* op = out + ((size_t)b * NC + c0) * KSEL;

#pragma unroll
    for (int j = 0; j < 8; ++j) {
        float4 v = __ldg(xp + (size_t)j * NE4);
        float* o = op + (size_t)j * KSEL;
        if (pos.x >= 0) o[pos.x] = v.x;
        if (pos.y >= 0) o[pos.y] = v.y;
        if (pos.z >= 0) o[pos.z] = v.z;
        if (pos.w >= 0) o[pos.w] = v.w;
    }
}

// ---------------------------------------------------------------------------
extern "C" void kernel_launch(void* const* d_in, const int* in_sizes, int n_in,
                              void* d_out, int out_size) {
    const float4* x4 = (const float4*)d_in[0];
    const void* ec = d_in[1];     // edges_count (int64 or int32; detected on device)
    float* out = (float*)d_out;

    score_kernel<<<dim3(NE4 / 32, NB), 256>>>(x4);
    select_kernel<<<NB, 1024>>>(ec);
    scatter_kernel<<<dim3(NE4 / 256, NC / 8, NB), 256>>>(x4, out);
}